// round 5
// baseline (speedup 1.0000x reference)
#include <cuda_runtime.h>

#define T_STEPS 730
#define N_GRID  8000
#define HALF    4000          // cells per "lane"; each thread does cell g and g+HALF
#define C       2             // cells per thread
#define NZ      1e-5f

__constant__ float c_LO[18] = {-3.f, 0.f, 0.f, 0.f, 0.f, 0.f, 0.f, 0.f, 0.005f, 1.f, 0.f, 1.f, 0.f, 1.f, 0.f, 0.f, 0.f, 0.f};
__constant__ float c_HI[18] = { 5.f,20.f, 1.f, 1.f, 5.f,50.f, 1.f, 1.f, 0.995f, 2000.f, 20.f, 300.f, 1.f, 5.f, 1.f, 1.f, 1.f, 1.f};

__global__ __launch_bounds__(32) void prms_kernel(
    const float* __restrict__ x,      // [T_STEPS, N_GRID, 3]
    const float* __restrict__ params, // [T_STEPS, N_GRID, 18]
    float* __restrict__ out)          // [T_STEPS, N_GRID]
{
    const int base = blockIdx.x * blockDim.x + threadIdx.x;
    if (base >= HALF) return;

    int g[C];
#pragma unroll
    for (int c = 0; c < C; c++) g[c] = base + c * HALF;

    // ---- per-cell parameters from the LAST timestep slice ----
    float tt[C], ddf[C], alpha[C], beta[C], stor[C], retip[C], cgw[C];
    float k1[C], k2[C], k3[C], k4[C], k5[C], k6[C];
    float scn[C], scx_m_scn[C], remx[C], inv_remx[C], smax[C], inv_smax[C];
    float inv_resmax[C], one_m_beta[C], one_m_alpha[C];

#pragma unroll
    for (int c = 0; c < C; c++) {
        const float* pp = params + ((size_t)(T_STEPS - 1) * N_GRID + g[c]) * 18;
        float pr[18];
#pragma unroll
        for (int i = 0; i < 18; i++) {
            float s = 1.0f / (1.0f + expf(-pp[i]));
            pr[i] = c_LO[i] + s * (c_HI[i] - c_LO[i]);
        }
        tt[c] = pr[0]; ddf[c] = pr[1]; alpha[c] = pr[2]; beta[c] = pr[3];
        stor[c] = pr[4]; retip[c] = pr[5];
        const float fscn = pr[6], scx = pr[7], flz = pr[8], stot = pr[9];
        cgw[c] = pr[10];
        const float resmax = pr[11];
        k1[c] = pr[12]; k2[c] = pr[13]; k3[c] = pr[14]; k4[c] = pr[15];
        k5[c] = pr[16]; k6[c] = pr[17];

        scn[c]        = fscn * scx;
        scx_m_scn[c]  = scx - scn[c];
        remx[c]       = (1.0f - flz) * stot;
        inv_remx[c]   = 1.0f / remx[c];
        smax[c]       = flz * stot;
        inv_smax[c]   = 1.0f / smax[c];
        inv_resmax[c] = 1.0f / resmax;
        one_m_beta[c] = 1.0f - beta[c];
        one_m_alpha[c]= 1.0f - alpha[c];
    }

    // ---- state ----
    float snow[C], xin[C], rstor[C], rechr[C], smav[C], res[C], gw[C];
#pragma unroll
    for (int c = 0; c < C; c++) {
        snow[c] = 0.001f; xin[c] = 0.001f; rstor[c] = 0.001f; rechr[c] = 0.001f;
        smav[c] = 0.001f; res[c] = 0.001f; gw[c] = 0.001f;
    }

    // ---- depth-2 register prefetch pipeline for x ----
    float Pb[2][C], Tb[2][C], Eb[2][C];
#pragma unroll
    for (int c = 0; c < C; c++) {
        const float* x0 = x + (size_t)g[c] * 3;                 // t = 0
        Pb[0][c] = x0[0]; Tb[0][c] = x0[1]; Eb[0][c] = x0[2];
        const float* x1 = x + ((size_t)N_GRID + g[c]) * 3;      // t = 1
        Pb[1][c] = x1[0]; Tb[1][c] = x1[1]; Eb[1][c] = x1[2];
    }

#pragma unroll 2
    for (int t = 0; t < T_STEPS; t++) {
        const int b = t & 1;
        float q[C];

        // FIRST: snapshot current forcing out of the buffer slot we are about
        // to overwrite (this ordering bug is what broke R3/R4).
        float Pcur[C], Tcur[C], Ecur[C];
#pragma unroll
        for (int c = 0; c < C; c++) {
            Pcur[c] = Pb[b][c]; Tcur[c] = Tb[b][c]; Ecur[c] = Eb[b][c];
        }

        // THEN: issue prefetch for t+2 into the freed slot (2 iterations to hide)
        const int tn = t + 2;
        if (tn < T_STEPS) {
#pragma unroll
            for (int c = 0; c < C; c++) {
                const float* xn = x + ((size_t)tn * N_GRID + g[c]) * 3;
                Pb[b][c] = xn[0]; Tb[b][c] = xn[1]; Eb[b][c] = xn[2];
            }
        }

#pragma unroll
        for (int c = 0; c < C; c++) {
            const float P  = Pcur[c];
            const float Tc = Tcur[c];
            const float Ep = Ecur[c];

            // ---- snow ----
            const float is_snow  = (Tc <= tt[c]) ? 1.0f : 0.0f;
            const float flux_ps  = P * is_snow;
            const float flux_pr  = P - flux_ps;            // == P*(1-is_snow), exact
            snow[c] += flux_ps;
            float flux_m = fmaxf(ddf[c] * (Tc - tt[c]), 0.0f);
            flux_m = fminf(flux_m, snow[c]);
            snow[c] = fmaxf(snow[c] - flux_m, NZ);

            // ---- interception ----
            const float flux_pim = flux_pr * one_m_beta[c];
            const float flux_psm = flux_pr * beta[c];
            const float flux_pby = flux_psm * one_m_alpha[c];
            const float flux_pin = flux_psm * alpha[c];
            xin[c] += flux_pin;
            const float flux_ptf = fmaxf(xin[c] - stor[c], 0.0f);
            xin[c] = fmaxf(xin[c] - flux_ptf, NZ);
            const float flux_ein = fminf(Ep * beta[c], xin[c]);
            xin[c] = fmaxf(xin[c] - flux_ein, NZ);

            // ---- impervious storage ----
            const float flux_mim = flux_m * one_m_beta[c];
            const float flux_msm = flux_m * beta[c];
            rstor[c] += flux_mim + flux_pim;
            const float flux_sas = fmaxf(rstor[c] - retip[c], 0.0f);
            rstor[c] = fmaxf(rstor[c] - flux_sas, NZ);
            const float flux_eim = fminf(one_m_beta[c] * Ep, rstor[c]);
            rstor[c] = fmaxf(rstor[c] - flux_eim, NZ);

            // ---- surface runoff / recharge ----
            const float sro_lin = fminf(fmaxf(fmaf(scx_m_scn[c], rechr[c] * inv_remx[c], scn[c]), 0.0f), 1.0f);
            const float inflow  = flux_msm + flux_ptf + flux_pby;
            const float flux_sro = sro_lin * inflow;
            const float flux_inf = inflow - flux_sro;
            rechr[c] += flux_inf;
            const float flux_pc = fmaxf(rechr[c] - remx[c], 0.0f);
            rechr[c] -= flux_pc;
            const float ep_net = Ep - flux_ein - flux_eim;
            const float evap_max_a = fmaxf(rechr[c] * inv_remx[c] * ep_net, 0.0f);
            const float flux_ea = fminf(evap_max_a, rechr[c]);
            rechr[c] = fmaxf(rechr[c] - flux_ea, NZ);

            // ---- soil moisture ----
            smav[c] += flux_pc;
            const float flux_excs = fmaxf(smav[c] - smax[c], 0.0f);
            smav[c] -= flux_excs;
            float transp = (rechr[c] < ep_net)
                             ? fmaxf(smav[c] * inv_smax[c] * (ep_net - flux_ea), 0.0f)
                             : 0.0f;
            transp = fminf(transp, smav[c]);
            smav[c] = fmaxf(smav[c] - transp, NZ);

            // ---- reservoir ----
            const float flux_sep  = fminf(cgw[c], flux_excs);
            const float flux_qres = fmaxf(flux_excs - flux_sep, 0.0f);
            res[c] += flux_qres;
            const float ratio = res[c] * inv_resmax[c];
            float flux_gad = k1[c] * powf(ratio, k2[c]);
            flux_gad = fminf(flux_gad, res[c]);
            res[c] = fmaxf(res[c] - flux_gad, NZ);
            float flux_ras = fminf(fmaf(k4[c] * res[c], res[c], k3[c] * res[c]), res[c]);
            res[c] = fmaxf(res[c] - flux_ras, NZ);

            // ---- groundwater ----
            gw[c] += flux_gad + flux_sep;
            const float flux_bas = k5[c] * gw[c];
            gw[c] = fmaxf(gw[c] - flux_bas, NZ);
            const float flux_snk = k6[c] * gw[c];
            gw[c] = fmaxf(gw[c] - flux_snk, NZ);

            // ---- streamflow ----
            q[c] = flux_sas + flux_sro + flux_bas + flux_ras;
        }

#pragma unroll
        for (int c = 0; c < C; c++)
            out[(size_t)t * N_GRID + g[c]] = q[c];
    }
}

extern "C" void kernel_launch(void* const* d_in, const int* in_sizes, int n_in,
                              void* d_out, int out_size) {
    // Identify inputs by element count (robust to ordering):
    //   x:          730*8000*3  = 17,520,000
    //   parameters: 730*8000*18 = 105,120,000
    const float* x = nullptr;
    const float* params = nullptr;
    for (int i = 0; i < n_in; i++) {
        if (in_sizes[i] == T_STEPS * N_GRID * 3)  x = (const float*)d_in[i];
        if (in_sizes[i] == T_STEPS * N_GRID * 18) params = (const float*)d_in[i];
    }
    float* out = (float*)d_out;

    const int threads = 32;                                // 1 warp per block
    const int blocks = (HALF + threads - 1) / threads;     // 125 blocks
    prms_kernel<<<blocks, threads>>>(x, params, out);
}